// round 12
// baseline (speedup 1.0000x reference)
#include <cuda_runtime.h>
#include <math.h>

#define N_NODES 100000
#define E_MAX   1600000
#define NBLK_SCAN 98   // ceil(N_NODES / 1024)

// ---------------------------------------------------------------------------
// Scratch (__device__ globals: allocation-free rule)
// ---------------------------------------------------------------------------
__device__ __align__(16) float g_agg[(size_t)N_NODES * 128]; // layer-1 mean
__device__ __align__(16) float g_y[(size_t)N_NODES * 64];    // h @ W2l^T
__device__ __align__(16) float g_z[(size_t)N_NODES * 64];    // h @ W2r^T + b2
__device__ int   g_row[N_NODES + 1];
__device__ int   g_cur[N_NODES];
__device__ int   g_col[E_MAX];
__device__ float g_inv[N_NODES];
__device__ int   g_bsum[NBLK_SCAN];
__device__ int   g_boff[NBLK_SCAN];
__device__ __align__(16) float g_wt1[256 * 128]; // k-major [k][o]: W1l||W1r
__device__ __align__(16) float g_wt2[256 * 64];  // k-major [k][o]: W2l||W2r
__device__ int   g_is64;

// ---------------------------------------------------------------------------
// Packed f32x2 helpers (Blackwell FFMA2 — PTX-only)
// ---------------------------------------------------------------------------
__device__ __forceinline__ void fma2(unsigned long long& d,
                                     unsigned long long a,
                                     unsigned long long b) {
    asm("fma.rn.f32x2 %0, %1, %2, %0;" : "+l"(d) : "l"(a), "l"(b));
}
__device__ __forceinline__ unsigned long long pk2(float x, float y) {
    unsigned long long r;
    asm("mov.b64 %0, {%1, %2};" : "=l"(r) : "f"(x), "f"(y));
    return r;
}
__device__ __forceinline__ void up2(unsigned long long v, float& x, float& y) {
    asm("mov.b64 {%0, %1}, %2;" : "=f"(x), "=f"(y) : "l"(v));
}

// ---------------------------------------------------------------------------
// Setup: block 0 detects int64 vs int32 edges; all blocks zero g_cur.
// ---------------------------------------------------------------------------
__global__ void setup_kernel(const unsigned int* __restrict__ e) {
    int i = blockIdx.x * blockDim.x + threadIdx.x;
    if (i < N_NODES) g_cur[i] = 0;
    if (blockIdx.x == 0) {
        __shared__ int nz;
        if (threadIdx.x == 0) nz = 0;
        __syncthreads();
        unsigned int acc = 0;
        for (int j = threadIdx.x; j < 1024; j += blockDim.x)
            acc |= e[2 * j + 1];
        if (acc) atomicOr(&nz, 1);
        __syncthreads();
        if (threadIdx.x == 0) g_is64 = (nz == 0) ? 1 : 0;
    }
}

// ---------------------------------------------------------------------------
// CSR build: histogram -> 3-phase full-chip scan -> fill
// ---------------------------------------------------------------------------
__global__ void hist_kernel(const void* __restrict__ edges, int E) {
    int i = blockIdx.x * blockDim.x + threadIdx.x;
    if (i >= E) return;
    int d = g_is64 ? (int)((const long long*)edges)[E + i]
                   : ((const int*)edges)[E + i];
    atomicAdd(&g_cur[d], 1);
}

// Phase 1: per-block sums; also folds the weight transpose (independent work).
__global__ void scan_sum_kernel(const float* __restrict__ W1l,
                                const float* __restrict__ W1r,
                                const float* __restrict__ W2l,
                                const float* __restrict__ W2r) {
    __shared__ int wsum[32];
    int tid = threadIdx.x;
    int i = blockIdx.x * 1024 + tid;
    int c = (i < N_NODES) ? g_cur[i] : 0;
    int v = c;
#pragma unroll
    for (int off = 16; off; off >>= 1) v += __shfl_xor_sync(~0u, v, off);
    if ((tid & 31) == 0) wsum[tid >> 5] = v;

    if (i < 256 * 128) {
        int k = i >> 7, o = i & 127;
        g_wt1[i] = (k < 128) ? W1l[o * 128 + k] : W1r[o * 128 + (k - 128)];
    }
    {
        int j = i - 256 * 128;
        if (j >= 0 && j < 256 * 64) {
            int k = j >> 6, o = j & 63;
            g_wt2[j] = (k < 128) ? W2l[o * 128 + k] : W2r[o * 128 + (k - 128)];
        }
    }

    __syncthreads();
    if (tid < 32) {
        int s = wsum[tid];
#pragma unroll
        for (int off = 16; off; off >>= 1) s += __shfl_xor_sync(~0u, s, off);
        if (tid == 0) g_bsum[blockIdx.x] = s;
    }
}

__global__ void scan_offsets_kernel() {
    __shared__ int wsum[4];
    int tid = threadIdx.x;
    int lane = tid & 31, w = tid >> 5;
    int v = (tid < NBLK_SCAN) ? g_bsum[tid] : 0;
    int inc = v;
#pragma unroll
    for (int off = 1; off < 32; off <<= 1) {
        int t = __shfl_up_sync(~0u, inc, off);
        if (lane >= off) inc += t;
    }
    if (lane == 31) wsum[w] = inc;
    __syncthreads();
    int woff = 0;
    for (int j = 0; j < w; j++) woff += wsum[j];
    int excl = woff + inc - v;
    if (tid < NBLK_SCAN) g_boff[tid] = excl;
    if (tid == NBLK_SCAN - 1) g_row[N_NODES] = excl + v;
}

__global__ void scan_write_kernel() {
    __shared__ int wsum[32];
    int tid = threadIdx.x;
    int lane = tid & 31, w = tid >> 5;
    int i = blockIdx.x * 1024 + tid;
    int c = (i < N_NODES) ? g_cur[i] : 0;
    int inc = c;
#pragma unroll
    for (int off = 1; off < 32; off <<= 1) {
        int t = __shfl_up_sync(~0u, inc, off);
        if (lane >= off) inc += t;
    }
    if (lane == 31) wsum[w] = inc;
    __syncthreads();
    if (tid < 32) {
        int v = wsum[tid];
        int winc = v;
#pragma unroll
        for (int off = 1; off < 32; off <<= 1) {
            int t = __shfl_up_sync(~0u, winc, off);
            if (tid >= off) winc += t;
        }
        wsum[tid] = winc - v;
    }
    __syncthreads();
    int excl = g_boff[blockIdx.x] + wsum[w] + inc - c;
    if (i < N_NODES) {
        g_row[i] = excl;
        g_cur[i] = excl;
        g_inv[i] = 1.0f / (float)max(c, 1);
    }
}

__global__ void fill_kernel(const void* __restrict__ edges, int E) {
    int i = blockIdx.x * blockDim.x + threadIdx.x;
    if (i >= E) return;
    int s, d;
    if (g_is64) {
        const long long* p = (const long long*)edges;
        s = (int)p[i]; d = (int)p[E + i];
    } else {
        const int* p = (const int*)edges;
        s = p[i]; d = p[E + i];
    }
    int pos = atomicAdd(&g_cur[d], 1);
    g_col[pos] = s;
}

// ---------------------------------------------------------------------------
// Gather-mean (128-wide): one warp per node.
// ---------------------------------------------------------------------------
__global__ void gather128_kernel(const float* __restrict__ x) {
    int wid = (blockIdx.x * blockDim.x + threadIdx.x) >> 5;
    int lane = threadIdx.x & 31;
    if (wid >= N_NODES) return;
    const float4* base = (const float4*)x;
    int beg = g_row[wid], end = g_row[wid + 1];
    float4 acc = make_float4(0.f, 0.f, 0.f, 0.f);
    int i = beg;
    for (; i + 2 <= end; i += 2) {
        int s0 = g_col[i], s1 = g_col[i + 1];
        float4 v0 = base[(size_t)s0 * 32 + lane];
        float4 v1 = base[(size_t)s1 * 32 + lane];
        acc.x += v0.x + v1.x; acc.y += v0.y + v1.y;
        acc.z += v0.z + v1.z; acc.w += v0.w + v1.w;
    }
    if (i < end) {
        int s = g_col[i];
        float4 v = base[(size_t)s * 32 + lane];
        acc.x += v.x; acc.y += v.y; acc.z += v.z; acc.w += v.w;
    }
    float inv = g_inv[wid];
    ((float4*)g_agg)[(size_t)wid * 32 + lane] =
        make_float4(acc.x * inv, acc.y * inv, acc.z * inv, acc.w * inv);
}

// ---------------------------------------------------------------------------
// Fused GEMM1 + y/z projections (FFMA2, software-pipelined):
//   h = relu( [mean||x] @ Wt1 + b1l )  (block-resident)
//   y = h @ W2l^T -> g_y ;  z = h @ W2r^T + b2l -> g_z
// Block 64 nodes x 128 outs, 256 threads, thread = 4 nodes x 8 outs.
// Phase 1: 4 k-tiles of 64, register-double-buffered staging; W2 (64KB,
// disjoint region) copied in 4 chunks folded into phase-1 iterations.
// Phase 2: single full-K=128 stage (a2 stride 130) + 128-kk loop.
// ---------------------------------------------------------------------------
#define SM_A_BYTES (64 * 130 * 8)                 // 66560
#define SM_W1_OFF  SM_A_BYTES
#define SM_W2_OFF  (SM_A_BYTES + 32768)           // 99328
#define G1_SMEM    (SM_W2_OFF + 65536)            // 164864

__global__ __launch_bounds__(256)
void gemm1_fused_kernel(const float* __restrict__ x,
                        const float* __restrict__ bl,
                        const float* __restrict__ b2) {
    extern __shared__ char smraw[];
    unsigned long long* a2 = (unsigned long long*)smraw; // p1 stride 65, p2 130
    float* w_s = (float*)(smraw + SM_W1_OFF);            // [64][128]
    float* w2s = (float*)(smraw + SM_W2_OFF);            // [128][128]

    int tid = threadIdx.x;
    int base = blockIdx.x * 64;
    int tx = tid & 15, ty = tid >> 4;
    int n0 = ty * 4, o0 = tx * 4;

    unsigned long long acc[4][4];
    {
        unsigned long long c0 = pk2(bl[o0], bl[o0 + 1]);
        unsigned long long c1 = pk2(bl[o0 + 2], bl[o0 + 3]);
        unsigned long long c2 = pk2(bl[64 + o0], bl[64 + o0 + 1]);
        unsigned long long c3 = pk2(bl[64 + o0 + 2], bl[64 + o0 + 3]);
#pragma unroll
        for (int i = 0; i < 4; i++) {
            acc[i][0] = c0; acc[i][1] = c1; acc[i][2] = c2; acc[i][3] = c3;
        }
    }

    float4 aV[4], wV[8];
    // ---- load + store k-tile 0 ----
    {
#pragma unroll
        for (int t = 0; t < 4; t++) {
            int idx = tid + t * 256, row = idx >> 4, c4 = idx & 15;
            int g = base + row;
            aV[t] = make_float4(0.f, 0.f, 0.f, 0.f);
            if (g < N_NODES)
                aV[t] = ((const float4*)(g_agg + (size_t)g * 128))[c4];
        }
        const float4* wsrc = (const float4*)g_wt1;
#pragma unroll
        for (int t = 0; t < 8; t++) wV[t] = wsrc[tid + t * 256];
#pragma unroll
        for (int t = 0; t < 4; t++) {
            int idx = tid + t * 256, row = idx >> 4, c4 = idx & 15;
            unsigned long long* d = a2 + row * 65 + c4 * 4;
            d[0] = pk2(aV[t].x, aV[t].x); d[1] = pk2(aV[t].y, aV[t].y);
            d[2] = pk2(aV[t].z, aV[t].z); d[3] = pk2(aV[t].w, aV[t].w);
        }
#pragma unroll
        for (int t = 0; t < 8; t++) ((float4*)w_s)[tid + t * 256] = wV[t];
    }
    __syncthreads();

    for (int kt = 0; kt < 4; kt++) {
        // prefetch k-tile kt+1 into registers (latency hides under compute)
        if (kt < 3) {
            const float* asrc = (kt + 1 < 2) ? g_agg : x;
            int koff = ((kt + 1) & 1) * 64;
#pragma unroll
            for (int t = 0; t < 4; t++) {
                int idx = tid + t * 256, row = idx >> 4, c4 = idx & 15;
                int g = base + row;
                aV[t] = make_float4(0.f, 0.f, 0.f, 0.f);
                if (g < N_NODES)
                    aV[t] = ((const float4*)(asrc + (size_t)g * 128 + koff))[c4];
            }
            const float4* wsrc = (const float4*)(g_wt1 + (kt + 1) * 64 * 128);
#pragma unroll
            for (int t = 0; t < 8; t++) wV[t] = wsrc[tid + t * 256];
        }
        // prefetch this iteration's W2 chunk (1024 float4 per kt, 4/thread)
        float4 w2c[4];
#pragma unroll
        for (int c = 0; c < 4; c++) {
            int d = tid + c * 256 + kt * 1024;
            int k = d >> 5, o4 = d & 31;
            w2c[c] = (o4 < 16)
                ? ((const float4*)g_wt2)[k * 16 + o4]
                : ((const float4*)g_wt2)[(128 + k) * 16 + (o4 - 16)];
        }

        // ---- compute 64 kk on resident tile ----
        {
            const unsigned long long* ap0 = a2 + (n0 + 0) * 65;
            const unsigned long long* ap1 = a2 + (n0 + 1) * 65;
            const unsigned long long* ap2 = a2 + (n0 + 2) * 65;
            const unsigned long long* ap3 = a2 + (n0 + 3) * 65;
#pragma unroll 4
            for (int kk = 0; kk < 64; kk++) {
                const float* wp = w_s + kk * 128;
                ulonglong2 w01 = *(const ulonglong2*)(wp + o0);
                ulonglong2 w23 = *(const ulonglong2*)(wp + 64 + o0);
                unsigned long long a0 = ap0[kk], a1 = ap1[kk];
                unsigned long long av2 = ap2[kk], a3 = ap3[kk];
                fma2(acc[0][0], a0, w01.x); fma2(acc[0][1], a0, w01.y);
                fma2(acc[0][2], a0, w23.x); fma2(acc[0][3], a0, w23.y);
                fma2(acc[1][0], a1, w01.x); fma2(acc[1][1], a1, w01.y);
                fma2(acc[1][2], a1, w23.x); fma2(acc[1][3], a1, w23.y);
                fma2(acc[2][0], av2, w01.x); fma2(acc[2][1], av2, w01.y);
                fma2(acc[2][2], av2, w23.x); fma2(acc[2][3], av2, w23.y);
                fma2(acc[3][0], a3, w01.x); fma2(acc[3][1], a3, w01.y);
                fma2(acc[3][2], a3, w23.x); fma2(acc[3][3], a3, w23.y);
            }
        }
        __syncthreads();

        // store W2 chunk (disjoint region; final sync before phase2 covers it)
#pragma unroll
        for (int c = 0; c < 4; c++)
            ((float4*)w2s)[tid + c * 256 + kt * 1024] = w2c[c];

        if (kt < 3) {
#pragma unroll
            for (int t = 0; t < 4; t++) {
                int idx = tid + t * 256, row = idx >> 4, c4 = idx & 15;
                unsigned long long* d = a2 + row * 65 + c4 * 4;
                d[0] = pk2(aV[t].x, aV[t].x); d[1] = pk2(aV[t].y, aV[t].y);
                d[2] = pk2(aV[t].z, aV[t].z); d[3] = pk2(aV[t].w, aV[t].w);
            }
#pragma unroll
            for (int t = 0; t < 8; t++) ((float4*)w_s)[tid + t * 256] = wV[t];
            __syncthreads();
        }
    }

    // ---- relu'd h, stage full-K dup pairs (stride 130) ----
    float hv[4][8];
#pragma unroll
    for (int i = 0; i < 4; i++) {
        up2(acc[i][0], hv[i][0], hv[i][1]); up2(acc[i][1], hv[i][2], hv[i][3]);
        up2(acc[i][2], hv[i][4], hv[i][5]); up2(acc[i][3], hv[i][6], hv[i][7]);
#pragma unroll
        for (int j = 0; j < 8; j++) hv[i][j] = fmaxf(hv[i][j], 0.f);
    }
#pragma unroll
    for (int i = 0; i < 4; i++) {
        unsigned long long* d = a2 + (n0 + i) * 130;
#pragma unroll
        for (int j = 0; j < 4; j++) {
            d[o0 + j] = pk2(hv[i][j], hv[i][j]);
            d[64 + o0 + j] = pk2(hv[i][4 + j], hv[i][4 + j]);
        }
    }
    __syncthreads();

    // ---- phase 2: y (outs 0..63) and z (outs 64..127), K=128 single pass ----
    unsigned long long acc2[4][4];
#pragma unroll
    for (int i = 0; i < 4; i++)
#pragma unroll
        for (int j = 0; j < 4; j++) acc2[i][j] = 0ull;

    {
        const unsigned long long* ap0 = a2 + (n0 + 0) * 130;
        const unsigned long long* ap1 = a2 + (n0 + 1) * 130;
        const unsigned long long* ap2 = a2 + (n0 + 2) * 130;
        const unsigned long long* ap3 = a2 + (n0 + 3) * 130;
#pragma unroll 4
        for (int kk = 0; kk < 128; kk++) {
            const float* wp = w2s + kk * 128;
            ulonglong2 w01 = *(const ulonglong2*)(wp + o0);          // y outs
            ulonglong2 w23 = *(const ulonglong2*)(wp + 64 + o0);     // z outs
            unsigned long long a0 = ap0[kk], a1 = ap1[kk];
            unsigned long long av2 = ap2[kk], a3 = ap3[kk];
            fma2(acc2[0][0], a0, w01.x); fma2(acc2[0][1], a0, w01.y);
            fma2(acc2[0][2], a0, w23.x); fma2(acc2[0][3], a0, w23.y);
            fma2(acc2[1][0], a1, w01.x); fma2(acc2[1][1], a1, w01.y);
            fma2(acc2[1][2], a1, w23.x); fma2(acc2[1][3], a1, w23.y);
            fma2(acc2[2][0], av2, w01.x); fma2(acc2[2][1], av2, w01.y);
            fma2(acc2[2][2], av2, w23.x); fma2(acc2[2][3], av2, w23.y);
            fma2(acc2[3][0], a3, w01.x); fma2(acc2[3][1], a3, w01.y);
            fma2(acc2[3][2], a3, w23.x); fma2(acc2[3][3], a3, w23.y);
        }
    }

    float bz0 = b2[o0], bz1 = b2[o0 + 1], bz2 = b2[o0 + 2], bz3 = b2[o0 + 3];
#pragma unroll
    for (int i = 0; i < 4; i++) {
        int g = base + n0 + i;
        if (g >= N_NODES) continue;
        float4 ry, rz;
        up2(acc2[i][0], ry.x, ry.y); up2(acc2[i][1], ry.z, ry.w);
        up2(acc2[i][2], rz.x, rz.y); up2(acc2[i][3], rz.z, rz.w);
        rz.x += bz0; rz.y += bz1; rz.z += bz2; rz.w += bz3;
        *(float4*)&g_y[(size_t)g * 64 + o0] = ry;
        *(float4*)&g_z[(size_t)g * 64 + o0] = rz;
    }
}

// ---------------------------------------------------------------------------
// Gather-mean (64-wide over g_y) + z add + fused log_softmax -> out.
// ---------------------------------------------------------------------------
__global__ void gather64_softmax_kernel(float* __restrict__ out) {
    int nid = (blockIdx.x * blockDim.x + threadIdx.x) >> 4;
    int lane = threadIdx.x & 15;
    if (nid >= N_NODES) return;
    const float4* base = (const float4*)g_y;
    int beg = g_row[nid], end = g_row[nid + 1];
    float4 acc = make_float4(0.f, 0.f, 0.f, 0.f);
    int i = beg;
    for (; i + 2 <= end; i += 2) {
        int s0 = g_col[i], s1 = g_col[i + 1];
        float4 v0 = base[(size_t)s0 * 16 + lane];
        float4 v1 = base[(size_t)s1 * 16 + lane];
        acc.x += v0.x + v1.x; acc.y += v0.y + v1.y;
        acc.z += v0.z + v1.z; acc.w += v0.w + v1.w;
    }
    if (i < end) {
        int s = g_col[i];
        float4 v = base[(size_t)s * 16 + lane];
        acc.x += v.x; acc.y += v.y; acc.z += v.z; acc.w += v.w;
    }
    float inv = g_inv[nid];
    float4 zv = ((const float4*)g_z)[(size_t)nid * 16 + lane];
    float4 v = make_float4(acc.x * inv + zv.x, acc.y * inv + zv.y,
                           acc.z * inv + zv.z, acc.w * inv + zv.w);

    float m = fmaxf(fmaxf(v.x, v.y), fmaxf(v.z, v.w));
#pragma unroll
    for (int off = 1; off < 16; off <<= 1)
        m = fmaxf(m, __shfl_xor_sync(0xffffffffu, m, off));
    float s = expf(v.x - m) + expf(v.y - m) + expf(v.z - m) + expf(v.w - m);
#pragma unroll
    for (int off = 1; off < 16; off <<= 1)
        s += __shfl_xor_sync(0xffffffffu, s, off);
    float lse = m + logf(s);
    ((float4*)out)[(size_t)nid * 16 + lane] =
        make_float4(v.x - lse, v.y - lse, v.z - lse, v.w - lse);
}

// ---------------------------------------------------------------------------
// Launch
// ---------------------------------------------------------------------------
extern "C" void kernel_launch(void* const* d_in, const int* in_sizes, int n_in,
                              void* d_out, int out_size) {
    const float* x   = (const float*)d_in[0];
    const void*  edg = d_in[1];
    const float* W1l = (const float*)d_in[2];
    const float* b1l = (const float*)d_in[3];
    const float* W1r = (const float*)d_in[4];
    const float* W2l = (const float*)d_in[5];
    const float* b2l = (const float*)d_in[6];
    const float* W2r = (const float*)d_in[7];
    float* out = (float*)d_out;

    int E = in_sizes[1] / 2;
    if (E > E_MAX) E = E_MAX;

    cudaFuncSetAttribute(gemm1_fused_kernel,
                         cudaFuncAttributeMaxDynamicSharedMemorySize, G1_SMEM);

    int eb = (E + 255) / 256;
    int g128_blocks = (N_NODES * 32 + 255) / 256;   // 12500
    int g64_blocks = (N_NODES * 16 + 255) / 256;    // 6250
    int g1_blocks = (N_NODES + 63) / 64;            // 1563

    setup_kernel<<<(N_NODES + 255) / 256, 256>>>((const unsigned int*)edg);
    hist_kernel<<<eb, 256>>>(edg, E);
    scan_sum_kernel<<<NBLK_SCAN, 1024>>>(W1l, W1r, W2l, W2r);
    scan_offsets_kernel<<<1, 128>>>();
    scan_write_kernel<<<NBLK_SCAN, 1024>>>();
    fill_kernel<<<eb, 256>>>(edg, E);

    gather128_kernel<<<g128_blocks, 256>>>(x);
    gemm1_fused_kernel<<<g1_blocks, 256, G1_SMEM>>>(x, b1l, b2l);
    gather64_softmax_kernel<<<g64_blocks, 256>>>(out);
}

// round 14
// speedup vs baseline: 1.0604x; 1.0604x over previous
#include <cuda_runtime.h>
#include <math.h>

#define N_NODES 100000
#define E_MAX   1600000
#define NBLK_SCAN 98   // ceil(N_NODES / 1024)

// ---------------------------------------------------------------------------
// Scratch (__device__ globals: allocation-free rule)
// ---------------------------------------------------------------------------
__device__ __align__(16) float g_agg[(size_t)N_NODES * 128]; // layer-1 mean
__device__ __align__(16) float g_y[(size_t)N_NODES * 64];    // h @ W2l^T
__device__ __align__(16) float g_z[(size_t)N_NODES * 64];    // h @ W2r^T + b2
__device__ int   g_row[N_NODES + 1];
__device__ int   g_cur[N_NODES];
__device__ int   g_col[E_MAX];
__device__ float g_inv[N_NODES];
__device__ int   g_bsum[NBLK_SCAN];
__device__ int   g_boff[NBLK_SCAN];
__device__ __align__(16) float g_wt1[256 * 128]; // k-major [k][o]: W1l||W1r
__device__ __align__(16) float g_wt2[256 * 64];  // k-major [k][o]: W2l||W2r
__device__ int   g_is64;

// ---------------------------------------------------------------------------
// Packed f32x2 helpers (Blackwell FFMA2 — PTX-only)
// ---------------------------------------------------------------------------
__device__ __forceinline__ void fma2(unsigned long long& d,
                                     unsigned long long a,
                                     unsigned long long b) {
    asm("fma.rn.f32x2 %0, %1, %2, %0;" : "+l"(d) : "l"(a), "l"(b));
}
__device__ __forceinline__ unsigned long long pk2(float x, float y) {
    unsigned long long r;
    asm("mov.b64 %0, {%1, %2};" : "=l"(r) : "f"(x), "f"(y));
    return r;
}
__device__ __forceinline__ void up2(unsigned long long v, float& x, float& y) {
    asm("mov.b64 {%0, %1}, %2;" : "=f"(x), "=f"(y) : "l"(v));
}

// ---------------------------------------------------------------------------
// Setup: block 0 detects int64 vs int32 edges; all blocks zero g_cur.
// ---------------------------------------------------------------------------
__global__ void setup_kernel(const unsigned int* __restrict__ e) {
    int i = blockIdx.x * blockDim.x + threadIdx.x;
    if (i < N_NODES) g_cur[i] = 0;
    if (blockIdx.x == 0) {
        __shared__ int nz;
        if (threadIdx.x == 0) nz = 0;
        __syncthreads();
        unsigned int acc = 0;
        for (int j = threadIdx.x; j < 1024; j += blockDim.x)
            acc |= e[2 * j + 1];
        if (acc) atomicOr(&nz, 1);
        __syncthreads();
        if (threadIdx.x == 0) g_is64 = (nz == 0) ? 1 : 0;
    }
}

// ---------------------------------------------------------------------------
// CSR build: histogram -> 3-phase full-chip scan -> fill
// ---------------------------------------------------------------------------
__global__ void hist_kernel(const void* __restrict__ edges, int E) {
    int i = blockIdx.x * blockDim.x + threadIdx.x;
    if (i >= E) return;
    int d = g_is64 ? (int)((const long long*)edges)[E + i]
                   : ((const int*)edges)[E + i];
    atomicAdd(&g_cur[d], 1);
}

// Phase 1: per-block sums; also folds the weight transpose (independent work).
__global__ void scan_sum_kernel(const float* __restrict__ W1l,
                                const float* __restrict__ W1r,
                                const float* __restrict__ W2l,
                                const float* __restrict__ W2r) {
    __shared__ int wsum[32];
    int tid = threadIdx.x;
    int i = blockIdx.x * 1024 + tid;
    int c = (i < N_NODES) ? g_cur[i] : 0;
    int v = c;
#pragma unroll
    for (int off = 16; off; off >>= 1) v += __shfl_xor_sync(~0u, v, off);
    if ((tid & 31) == 0) wsum[tid >> 5] = v;

    if (i < 256 * 128) {
        int k = i >> 7, o = i & 127;
        g_wt1[i] = (k < 128) ? W1l[o * 128 + k] : W1r[o * 128 + (k - 128)];
    }
    {
        int j = i - 256 * 128;
        if (j >= 0 && j < 256 * 64) {
            int k = j >> 6, o = j & 63;
            g_wt2[j] = (k < 128) ? W2l[o * 128 + k] : W2r[o * 128 + (k - 128)];
        }
    }

    __syncthreads();
    if (tid < 32) {
        int s = wsum[tid];
#pragma unroll
        for (int off = 16; off; off >>= 1) s += __shfl_xor_sync(~0u, s, off);
        if (tid == 0) g_bsum[blockIdx.x] = s;
    }
}

__global__ void scan_offsets_kernel() {
    __shared__ int wsum[4];
    int tid = threadIdx.x;
    int lane = tid & 31, w = tid >> 5;
    int v = (tid < NBLK_SCAN) ? g_bsum[tid] : 0;
    int inc = v;
#pragma unroll
    for (int off = 1; off < 32; off <<= 1) {
        int t = __shfl_up_sync(~0u, inc, off);
        if (lane >= off) inc += t;
    }
    if (lane == 31) wsum[w] = inc;
    __syncthreads();
    int woff = 0;
    for (int j = 0; j < w; j++) woff += wsum[j];
    int excl = woff + inc - v;
    if (tid < NBLK_SCAN) g_boff[tid] = excl;
    if (tid == NBLK_SCAN - 1) g_row[N_NODES] = excl + v;
}

__global__ void scan_write_kernel() {
    __shared__ int wsum[32];
    int tid = threadIdx.x;
    int lane = tid & 31, w = tid >> 5;
    int i = blockIdx.x * 1024 + tid;
    int c = (i < N_NODES) ? g_cur[i] : 0;
    int inc = c;
#pragma unroll
    for (int off = 1; off < 32; off <<= 1) {
        int t = __shfl_up_sync(~0u, inc, off);
        if (lane >= off) inc += t;
    }
    if (lane == 31) wsum[w] = inc;
    __syncthreads();
    if (tid < 32) {
        int v = wsum[tid];
        int winc = v;
#pragma unroll
        for (int off = 1; off < 32; off <<= 1) {
            int t = __shfl_up_sync(~0u, winc, off);
            if (tid >= off) winc += t;
        }
        wsum[tid] = winc - v;
    }
    __syncthreads();
    int excl = g_boff[blockIdx.x] + wsum[w] + inc - c;
    if (i < N_NODES) {
        g_row[i] = excl;
        g_cur[i] = excl;
        g_inv[i] = 1.0f / (float)max(c, 1);
    }
}

__global__ void fill_kernel(const void* __restrict__ edges, int E) {
    int i = blockIdx.x * blockDim.x + threadIdx.x;
    if (i >= E) return;
    int s, d;
    if (g_is64) {
        const long long* p = (const long long*)edges;
        s = (int)p[i]; d = (int)p[E + i];
    } else {
        const int* p = (const int*)edges;
        s = p[i]; d = p[E + i];
    }
    int pos = atomicAdd(&g_cur[d], 1);
    g_col[pos] = s;
}

// ---------------------------------------------------------------------------
// Gather-mean (128-wide): one warp per node.
// ---------------------------------------------------------------------------
__global__ void gather128_kernel(const float* __restrict__ x) {
    int wid = (blockIdx.x * blockDim.x + threadIdx.x) >> 5;
    int lane = threadIdx.x & 31;
    if (wid >= N_NODES) return;
    const float4* base = (const float4*)x;
    int beg = g_row[wid], end = g_row[wid + 1];
    float4 acc = make_float4(0.f, 0.f, 0.f, 0.f);
    int i = beg;
    for (; i + 2 <= end; i += 2) {
        int s0 = g_col[i], s1 = g_col[i + 1];
        float4 v0 = base[(size_t)s0 * 32 + lane];
        float4 v1 = base[(size_t)s1 * 32 + lane];
        acc.x += v0.x + v1.x; acc.y += v0.y + v1.y;
        acc.z += v0.z + v1.z; acc.w += v0.w + v1.w;
    }
    if (i < end) {
        int s = g_col[i];
        float4 v = base[(size_t)s * 32 + lane];
        acc.x += v.x; acc.y += v.y; acc.z += v.z; acc.w += v.w;
    }
    float inv = g_inv[wid];
    ((float4*)g_agg)[(size_t)wid * 32 + lane] =
        make_float4(acc.x * inv, acc.y * inv, acc.z * inv, acc.w * inv);
}

// ---------------------------------------------------------------------------
// Fused GEMM1 + y/z projections (R7 structure, register-dieted):
//   h = relu( [mean||x] @ Wt1 + b1l )   (lives in acc until phase 2)
//   y = h @ W2l^T          -> g_y
//   z = h @ W2r^T + b2l    -> g_z
// Block 64 nodes x 128 outs, BK=64, 256 threads. Phase 2 reuses the same
// smem buffers, staging h dup-pairs (unpacked+relu'd from acc on the fly)
// + W2 halves in two K=64 passes. __launch_bounds__(256,2) for 2 CTAs/SM.
// ---------------------------------------------------------------------------
#define G1_SMEM (64 * 65 * 8 + 64 * 128 * 4)

__global__ __launch_bounds__(256, 2)
void gemm1_fused_kernel(const float* __restrict__ x,
                        const float* __restrict__ bl,
                        const float* __restrict__ b2) {
    extern __shared__ unsigned long long sm_u[];
    unsigned long long* a2 = sm_u;              // [64][65] dup pairs
    float* w_s = (float*)(sm_u + 64 * 65);      // [64][128]

    int tid = threadIdx.x;
    int base = blockIdx.x * 64;
    int tx = tid & 15, ty = tid >> 4;
    int n0 = ty * 4, o0 = tx * 4;

    unsigned long long acc[4][4];
    {
        unsigned long long c0 = pk2(bl[o0], bl[o0 + 1]);
        unsigned long long c1 = pk2(bl[o0 + 2], bl[o0 + 3]);
        unsigned long long c2 = pk2(bl[64 + o0], bl[64 + o0 + 1]);
        unsigned long long c3 = pk2(bl[64 + o0 + 2], bl[64 + o0 + 3]);
#pragma unroll
        for (int i = 0; i < 4; i++) {
            acc[i][0] = c0; acc[i][1] = c1; acc[i][2] = c2; acc[i][3] = c3;
        }
    }

    for (int kt = 0; kt < 4; kt++) {
        const float* asrc = (kt < 2) ? g_agg : x;
        int koff = (kt & 1) * 64;
#pragma unroll
        for (int t = 0; t < 4; t++) {
            int idx = tid + t * 256;            // 0..1023
            int row = idx >> 4, c4 = idx & 15;
            int g = base + row;
            float4 v = make_float4(0.f, 0.f, 0.f, 0.f);
            if (g < N_NODES)
                v = ((const float4*)(asrc + (size_t)g * 128 + koff))[c4];
            unsigned long long* d = a2 + row * 65 + c4 * 4;
            d[0] = pk2(v.x, v.x); d[1] = pk2(v.y, v.y);
            d[2] = pk2(v.z, v.z); d[3] = pk2(v.w, v.w);
        }
        const float4* wsrc = (const float4*)(g_wt1 + kt * 64 * 128);
#pragma unroll
        for (int t = 0; t < 8; t++) {
            int idx = tid + t * 256;            // 0..2047
            ((float4*)w_s)[idx] = wsrc[idx];
        }
        __syncthreads();

        const unsigned long long* ap0 = a2 + (n0 + 0) * 65;
        const unsigned long long* ap1 = a2 + (n0 + 1) * 65;
        const unsigned long long* ap2 = a2 + (n0 + 2) * 65;
        const unsigned long long* ap3 = a2 + (n0 + 3) * 65;
#pragma unroll 4
        for (int kk = 0; kk < 64; kk++) {
            const float* wp = w_s + kk * 128;
            ulonglong2 w01 = *(const ulonglong2*)(wp + o0);
            ulonglong2 w23 = *(const ulonglong2*)(wp + 64 + o0);
            unsigned long long a0 = ap0[kk], a1 = ap1[kk];
            unsigned long long av2 = ap2[kk], a3 = ap3[kk];
            fma2(acc[0][0], a0, w01.x); fma2(acc[0][1], a0, w01.y);
            fma2(acc[0][2], a0, w23.x); fma2(acc[0][3], a0, w23.y);
            fma2(acc[1][0], a1, w01.x); fma2(acc[1][1], a1, w01.y);
            fma2(acc[1][2], a1, w23.x); fma2(acc[1][3], a1, w23.y);
            fma2(acc[2][0], av2, w01.x); fma2(acc[2][1], av2, w01.y);
            fma2(acc[2][2], av2, w23.x); fma2(acc[2][3], av2, w23.y);
            fma2(acc[3][0], a3, w01.x); fma2(acc[3][1], a3, w01.y);
            fma2(acc[3][2], a3, w23.x); fma2(acc[3][3], a3, w23.y);
        }
        __syncthreads();
    }

    // Phase 2: y (outs 0..63 <- W2l) and z (outs 64..127 <- W2r), K=128 in
    // 2 halves. h is unpacked + relu'd from acc at staging time (no hv regs).
    unsigned long long acc2[4][4];
#pragma unroll
    for (int i = 0; i < 4; i++)
#pragma unroll
        for (int j = 0; j < 4; j++) acc2[i][j] = 0ull;

#pragma unroll
    for (int kh = 0; kh < 2; kh++) {
        // stage h dup-pairs for this K-half directly from acc (+bias was
        // already folded into acc's init; relu applied here)
#pragma unroll
        for (int i = 0; i < 4; i++) {
            float p0, p1, p2, p3;
            up2(acc[i][kh * 2 + 0], p0, p1);
            up2(acc[i][kh * 2 + 1], p2, p3);
            p0 = fmaxf(p0, 0.f); p1 = fmaxf(p1, 0.f);
            p2 = fmaxf(p2, 0.f); p3 = fmaxf(p3, 0.f);
            unsigned long long* d = a2 + (n0 + i) * 65 + o0;
            d[0] = pk2(p0, p0); d[1] = pk2(p1, p1);
            d[2] = pk2(p2, p2); d[3] = pk2(p3, p3);
        }
        // stage combined W2 half: w_s[kk][o], o<64 = W2l, o>=64 = W2r
#pragma unroll
        for (int t = 0; t < 8; t++) {
            int idx = tid + t * 256;            // 0..2047 float4s
            int kk = idx >> 5, o4 = idx & 31;
            float4 wv;
            if (o4 < 16)
                wv = *(const float4*)&g_wt2[(kh * 64 + kk) * 64 + o4 * 4];
            else
                wv = *(const float4*)&g_wt2[(128 + kh * 64 + kk) * 64 + (o4 - 16) * 4];
            ((float4*)w_s)[idx] = wv;
        }
        __syncthreads();

        const unsigned long long* ap0 = a2 + (n0 + 0) * 65;
        const unsigned long long* ap1 = a2 + (n0 + 1) * 65;
        const unsigned long long* ap2 = a2 + (n0 + 2) * 65;
        const unsigned long long* ap3 = a2 + (n0 + 3) * 65;
#pragma unroll 4
        for (int kk = 0; kk < 64; kk++) {
            const float* wp = w_s + kk * 128;
            ulonglong2 w01 = *(const ulonglong2*)(wp + o0);          // y outs
            ulonglong2 w23 = *(const ulonglong2*)(wp + 64 + o0);     // z outs
            unsigned long long a0 = ap0[kk], a1 = ap1[kk];
            unsigned long long av2 = ap2[kk], a3 = ap3[kk];
            fma2(acc2[0][0], a0, w01.x); fma2(acc2[0][1], a0, w01.y);
            fma2(acc2[0][2], a0, w23.x); fma2(acc2[0][3], a0, w23.y);
            fma2(acc2[1][0], a1, w01.x); fma2(acc2[1][1], a1, w01.y);
            fma2(acc2[1][2], a1, w23.x); fma2(acc2[1][3], a1, w23.y);
            fma2(acc2[2][0], av2, w01.x); fma2(acc2[2][1], av2, w01.y);
            fma2(acc2[2][2], av2, w23.x); fma2(acc2[2][3], av2, w23.y);
            fma2(acc2[3][0], a3, w01.x); fma2(acc2[3][1], a3, w01.y);
            fma2(acc2[3][2], a3, w23.x); fma2(acc2[3][3], a3, w23.y);
        }
        __syncthreads();
    }

    float bz0 = b2[o0], bz1 = b2[o0 + 1], bz2 = b2[o0 + 2], bz3 = b2[o0 + 3];
#pragma unroll
    for (int i = 0; i < 4; i++) {
        int g = base + n0 + i;
        if (g >= N_NODES) continue;
        float4 ry, rz;
        up2(acc2[i][0], ry.x, ry.y); up2(acc2[i][1], ry.z, ry.w);
        up2(acc2[i][2], rz.x, rz.y); up2(acc2[i][3], rz.z, rz.w);
        rz.x += bz0; rz.y += bz1; rz.z += bz2; rz.w += bz3;
        *(float4*)&g_y[(size_t)g * 64 + o0] = ry;
        *(float4*)&g_z[(size_t)g * 64 + o0] = rz;
    }
}

// ---------------------------------------------------------------------------
// Gather-mean (64-wide over g_y) + z add + fused log_softmax -> out.
// ---------------------------------------------------------------------------
__global__ void gather64_softmax_kernel(float* __restrict__ out) {
    int nid = (blockIdx.x * blockDim.x + threadIdx.x) >> 4;
    int lane = threadIdx.x & 15;
    if (nid >= N_NODES) return;
    const float4* base = (const float4*)g_y;
    int beg = g_row[nid], end = g_row[nid + 1];
    float4 acc = make_float4(0.f, 0.f, 0.f, 0.f);
    int i = beg;
    for (; i + 2 <= end; i += 2) {
        int s0 = g_col[i], s1 = g_col[i + 1];
        float4 v0 = base[(size_t)s0 * 16 + lane];
        float4 v1 = base[(size_t)s1 * 16 + lane];
        acc.x += v0.x + v1.x; acc.y += v0.y + v1.y;
        acc.z += v0.z + v1.z; acc.w += v0.w + v1.w;
    }
    if (i < end) {
        int s = g_col[i];
        float4 v = base[(size_t)s * 16 + lane];
        acc.x += v.x; acc.y += v.y; acc.z += v.z; acc.w += v.w;
    }
    float inv = g_inv[nid];
    float4 zv = ((const float4*)g_z)[(size_t)nid * 16 + lane];
    float4 v = make_float4(acc.x * inv + zv.x, acc.y * inv + zv.y,
                           acc.z * inv + zv.z, acc.w * inv + zv.w);

    float m = fmaxf(fmaxf(v.x, v.y), fmaxf(v.z, v.w));
#pragma unroll
    for (int off = 1; off < 16; off <<= 1)
        m = fmaxf(m, __shfl_xor_sync(0xffffffffu, m, off));
    float s = expf(v.x - m) + expf(v.y - m) + expf(v.z - m) + expf(v.w - m);
#pragma unroll
    for (int off = 1; off < 16; off <<= 1)
        s += __shfl_xor_sync(0xffffffffu, s, off);
    float lse = m + logf(s);
    ((float4*)out)[(size_t)nid * 16 + lane] =
        make_float4(v.x - lse, v.y - lse, v.z - lse, v.w - lse);
}

// ---------------------------------------------------------------------------
// Launch
// ---------------------------------------------------------------------------
extern "C" void kernel_launch(void* const* d_in, const int* in_sizes, int n_in,
                              void* d_out, int out_size) {
    const float* x   = (const float*)d_in[0];
    const void*  edg = d_in[1];
    const float* W1l = (const float*)d_in[2];
    const float* b1l = (const float*)d_in[3];
    const float* W1r = (const float*)d_in[4];
    const float* W2l = (const float*)d_in[5];
    const float* b2l = (const float*)d_in[6];
    const float* W2r = (const float*)d_in[7];
    float* out = (float*)d_out;

    int E = in_sizes[1] / 2;
    if (E > E_MAX) E = E_MAX;

    cudaFuncSetAttribute(gemm1_fused_kernel,
                         cudaFuncAttributeMaxDynamicSharedMemorySize, G1_SMEM);

    int eb = (E + 255) / 256;
    int g128_blocks = (N_NODES * 32 + 255) / 256;   // 12500
    int g64_blocks = (N_NODES * 16 + 255) / 256;    // 6250
    int g1_blocks = (N_NODES + 63) / 64;            // 1563

    setup_kernel<<<(N_NODES + 255) / 256, 256>>>((const unsigned int*)edg);
    hist_kernel<<<eb, 256>>>(edg, E);
    scan_sum_kernel<<<NBLK_SCAN, 1024>>>(W1l, W1r, W2l, W2r);
    scan_offsets_kernel<<<1, 128>>>();
    scan_write_kernel<<<NBLK_SCAN, 1024>>>();
    fill_kernel<<<eb, 256>>>(edg, E);

    gather128_kernel<<<g128_blocks, 256>>>(x);
    gemm1_fused_kernel<<<g1_blocks, 256, G1_SMEM>>>(x, b1l, b2l);
    gather64_softmax_kernel<<<g64_blocks, 256>>>(out);
}